// round 12
// baseline (speedup 1.0000x reference)
#include <cuda_runtime.h>
#include <cstdint>
#include <cstddef>

#define NNODES 100000
#define NEDGES 20000
#define D 128

// ---- scratch (device globals: allocation-free) ----
__device__ __align__(16) float g_y[(size_t)NNODES * D];      // x @ conv_W
__device__ __align__(16) float g_efeat[(size_t)NEDGES * D];  // hyperedge accum
__device__ int   g_degn[NNODES];
__device__ int   g_dege[NEDGES];
__device__ float g_invn[NNODES];
__device__ float g_inve[NEDGES];

// ---- zero e_feat + degree counters ----
__global__ __launch_bounds__(256) void k_zero() {
    int i = blockIdx.x * blockDim.x + threadIdx.x;
    const int nef4 = (NEDGES * D) / 4;  // 640000 float4
    if (i < nef4) {
        ((float4*)g_efeat)[i] = make_float4(0.f, 0.f, 0.f, 0.f);
    }
    if (i < NNODES) g_degn[i] = 0;
    if (i < NEDGES) g_dege[i] = 0;
}

// ---- degree counts ----
__global__ __launch_bounds__(256) void k_degree(const int* __restrict__ ni,
                                                const int* __restrict__ ei, int nnz) {
    int i = blockIdx.x * blockDim.x + threadIdx.x;
    if (i < nnz) {
        atomicAdd(&g_degn[ni[i]], 1);
        atomicAdd(&g_dege[ei[i]], 1);
    }
}

// ---- 1/deg ----
__global__ __launch_bounds__(256) void k_inv() {
    int i = blockIdx.x * blockDim.x + threadIdx.x;
    if (i < NNODES) {
        int d = g_degn[i];
        g_invn[i] = d > 0 ? 1.0f / (float)d : 0.0f;
    }
    if (i < NEDGES) {
        int d = g_dege[i];
        g_inve[i] = d > 0 ? 1.0f / (float)d : 0.0f;
    }
}

// ---- tf32 helpers ----
__device__ __forceinline__ uint32_t f2tf32(float f) {
    uint32_t r;
    asm("cvt.rna.tf32.f32 %0, %1;" : "=r"(r) : "f"(f));
    return r;
}

__device__ __forceinline__ void mma_tf32(float* c, uint32_t a0, uint32_t a1,
                                         uint32_t a2, uint32_t a3,
                                         uint32_t b0, uint32_t b1) {
    asm volatile("mma.sync.aligned.m16n8k8.row.col.f32.tf32.tf32.f32 "
                 "{%0,%1,%2,%3}, {%4,%5,%6,%7}, {%8,%9}, {%0,%1,%2,%3};"
                 : "+f"(c[0]), "+f"(c[1]), "+f"(c[2]), "+f"(c[3])
                 : "r"(a0), "r"(a1), "r"(a2), "r"(a3), "r"(b0), "r"(b1));
}

// ---- fused dual GEMM via 3xTF32 tensor-core MMA ----
// C1 = A@B1 ; C2 = A@B2 + (bias1+bias2).  Block: 64 rows x 128 cols x 2 mats.
// 8 warps: warp = (mat, m-half of 32 rows, n-half of 64 cols).
// Split each operand into tf32 hi + lo; accumulate hi*hi + hi*lo + lo*hi.
__global__ __launch_bounds__(256, 2) void k_gemm_mma(
    const float* __restrict__ A,
    const float* __restrict__ B1, const float* __restrict__ B2,
    const float* __restrict__ bias1, const float* __restrict__ bias2,
    float* __restrict__ C1, float* __restrict__ C2, int M) {
    // A: fragment-major: word(m,k) = m*8 + (k&3)*2 + (k>>2)   [part][512]
    // B: xor-swizzled:   word(k,n) = k*128 + (n&7)*16 + ((((n>>5)&3)^(k&3))<<2) + ((n>>3)&3)
    __shared__ uint32_t As[2][64 * 8];
    __shared__ uint32_t Bs[2][2][8 * 128];   // [mat][part]

    const int t    = threadIdx.x;
    const int lane = t & 31;
    const int wid  = t >> 5;
    const int mat  = wid >> 2;        // 0 -> C1 (conv), 1 -> C2 (res+bias)
    const int mh   = (wid >> 1) & 1;  // rows mh*32 .. +32
    const int nh   = wid & 1;         // cols nh*64 .. +64
    const int q    = lane & 3;
    const int r    = lane >> 2;
    const int row0 = blockIdx.x * 64;

    // global-load mapping
    const int tm  = t & 63;           // A row within tile
    const int tk2 = (t >> 6) * 2;     // A k-pair base (0,2,4,6)
    int arow = row0 + tm;
    if (arow >= M) arow = M - 1;      // clamp; stores are guarded
    const float* Aptr = A + (size_t)arow * D + tk2;
    const int kb = t >> 5;            // B k-row (0..7)
    const int nb = lane * 4;          // B n base

    float acc[2][8][4];
#pragma unroll
    for (int f = 0; f < 2; f++)
#pragma unroll
        for (int nt = 0; nt < 8; nt++)
#pragma unroll
            for (int j = 0; j < 4; j++) acc[f][nt][j] = 0.f;

    // prefetch k-chunk 0
    float2 a_pf  = *(const float2*)(Aptr);
    float4 b1_pf = *(const float4*)&B1[(size_t)kb * D + nb];
    float4 b2_pf = *(const float4*)&B2[(size_t)kb * D + nb];

    const int wA0 = tm * 8 + (tk2 & 3) * 2 + (tk2 >> 2);
    const int wA1 = tm * 8 + ((tk2 + 1) & 3) * 2 + ((tk2 + 1) >> 2);

    for (int kk = 0; kk < 16; kk++) {
        // ---- stage prefetched chunk into SMEM (hi/lo split) ----
        {
            uint32_t h0 = f2tf32(a_pf.x);
            uint32_t h1 = f2tf32(a_pf.y);
            As[0][wA0] = h0;
            As[0][wA1] = h1;
            As[1][wA0] = f2tf32(a_pf.x - __uint_as_float(h0));
            As[1][wA1] = f2tf32(a_pf.y - __uint_as_float(h1));
        }
#pragma unroll
        for (int j = 0; j < 4; j++) {
            int n = nb + j;
            int w = kb * 128 + (n & 7) * 16 +
                    ((((n >> 5) & 3) ^ (kb & 3)) << 2) + ((n >> 3) & 3);
            float v1 = (&b1_pf.x)[j];
            float v2 = (&b2_pf.x)[j];
            uint32_t h1 = f2tf32(v1);
            uint32_t h2 = f2tf32(v2);
            Bs[0][0][w] = h1;
            Bs[0][1][w] = f2tf32(v1 - __uint_as_float(h1));
            Bs[1][0][w] = h2;
            Bs[1][1][w] = f2tf32(v2 - __uint_as_float(h2));
        }
        __syncthreads();

        if (kk + 1 < 16) {
            a_pf  = *(const float2*)(Aptr + (kk + 1) * 8);
            b1_pf = *(const float4*)&B1[(size_t)((kk + 1) * 8 + kb) * D + nb];
            b2_pf = *(const float4*)&B2[(size_t)((kk + 1) * 8 + kb) * D + nb];
        }

        // ---- A fragments: (a0,a2) and (a1,a3) as LDS.64 pairs ----
        uint2 afr[2][2][2];  // [part][frag][rowhalf] -> .x = k=q, .y = k=q+4
        const uint2* A64h = (const uint2*)As[0];
        const uint2* A64l = (const uint2*)As[1];
#pragma unroll
        for (int f = 0; f < 2; f++) {
            int rb = mh * 32 + f * 16 + r;
            afr[0][f][0] = A64h[rb * 4 + q];
            afr[0][f][1] = A64h[(rb + 8) * 4 + q];
            afr[1][f][0] = A64l[rb * 4 + q];
            afr[1][f][1] = A64l[(rb + 8) * 4 + q];
        }

        // ---- 3 terms: (hiA,hiB), (hiA,loB), (loA,hiB) ----
#pragma unroll
        for (int term = 0; term < 3; term++) {
            const int pa = (term == 2) ? 1 : 0;
            const int pb = (term == 1) ? 1 : 0;
            const uint32_t* Bp = Bs[mat][pb];
            uint4 b0f[2], b1f[2];
#pragma unroll
            for (int ci = 0; ci < 2; ci++) {
                int cc = nh * 2 + ci;
                int w0 = q * 128 + r * 16 + ((cc ^ q) << 2);
                b0f[ci] = *(const uint4*)&Bp[w0];
                b1f[ci] = *(const uint4*)&Bp[w0 + 512];  // k = q+4 row
            }
#pragma unroll
            for (int f = 0; f < 2; f++) {
                uint2 alo = afr[pa][f][0];
                uint2 ahi = afr[pa][f][1];
#pragma unroll
                for (int nt = 0; nt < 8; nt++) {
                    uint32_t b0 = (&b0f[nt >> 2].x)[nt & 3];
                    uint32_t b1 = (&b1f[nt >> 2].x)[nt & 3];
                    mma_tf32(acc[f][nt], alo.x, ahi.x, alo.y, ahi.y, b0, b1);
                }
            }
        }
        __syncthreads();
    }

    // ---- epilogue ----
#pragma unroll
    for (int f = 0; f < 2; f++) {
        int rA = row0 + mh * 32 + f * 16 + r;
#pragma unroll
        for (int nt = 0; nt < 8; nt++) {
            int col = nh * 64 + nt * 8 + 2 * q;
            if (mat == 0) {
                if (rA < M)
                    *(float2*)&C1[(size_t)rA * D + col] =
                        make_float2(acc[f][nt][0], acc[f][nt][1]);
                if (rA + 8 < M)
                    *(float2*)&C1[(size_t)(rA + 8) * D + col] =
                        make_float2(acc[f][nt][2], acc[f][nt][3]);
            } else {
                float bx = bias1[col] + bias2[col];
                float by = bias1[col + 1] + bias2[col + 1];
                if (rA < M)
                    *(float2*)&C2[(size_t)rA * D + col] =
                        make_float2(acc[f][nt][0] + bx, acc[f][nt][1] + by);
                if (rA + 8 < M)
                    *(float2*)&C2[(size_t)(rA + 8) * D + col] =
                        make_float2(acc[f][nt][2] + bx, acc[f][nt][3] + by);
            }
        }
    }
}

__device__ __forceinline__ void red_add_v4(float* p, float4 v) {
    asm volatile("red.global.add.v4.f32 [%0], {%1, %2, %3, %4};"
                 :: "l"(p), "f"(v.x), "f"(v.y), "f"(v.z), "f"(v.w)
                 : "memory");
}

// ---- pass 1: e_feat[edge] += y[node]  (one warp per nz, float4/lane) ----
__global__ __launch_bounds__(256) void k_scatter_edge(const int* __restrict__ ni,
                                                      const int* __restrict__ ei, int nnz) {
    int w = blockIdx.x * 8 + (threadIdx.x >> 5);
    int lane = threadIdx.x & 31;
    if (w >= nnz) return;
    int node = __ldg(&ni[w]);
    int edge = __ldg(&ei[w]);
    float4 v = *(const float4*)&g_y[(size_t)node * D + lane * 4];
    red_add_v4(&g_efeat[(size_t)edge * D + lane * 4], v);
}

// ---- pass 2: out[node] += e_feat[edge] * inv_e[edge] * inv_n[node] ----
__global__ __launch_bounds__(256) void k_scatter_node(const int* __restrict__ ni,
                                                      const int* __restrict__ ei,
                                                      float* __restrict__ out, int nnz) {
    int w = blockIdx.x * 8 + (threadIdx.x >> 5);
    int lane = threadIdx.x & 31;
    if (w >= nnz) return;
    int node = __ldg(&ni[w]);
    int edge = __ldg(&ei[w]);
    float s = g_inve[edge] * g_invn[node];
    float4 v = *(const float4*)&g_efeat[(size_t)edge * D + lane * 4];
    v.x *= s; v.y *= s; v.z *= s; v.w *= s;
    red_add_v4(&out[(size_t)node * D + lane * 4], v);
}

extern "C" void kernel_launch(void* const* d_in, const int* in_sizes, int n_in,
                              void* d_out, int out_size) {
    const float* x      = (const float*)d_in[0];
    const int*   ni     = (const int*)d_in[1];
    const int*   ei     = (const int*)d_in[2];
    const float* conv_W = (const float*)d_in[3];
    const float* conv_b = (const float*)d_in[4];
    const float* res_W  = (const float*)d_in[5];
    const float* res_b  = (const float*)d_in[6];
    float* out = (float*)d_out;

    const int M   = in_sizes[0] / D;   // 100000
    const int nnz = in_sizes[1];       // 600000

    void* yptr = nullptr;
    cudaGetSymbolAddress(&yptr, g_y);

    // zero scratch (e_feat float4s dominate: 640000 elems)
    k_zero<<<(640000 + 255) / 256, 256>>>();

    // degrees
    k_degree<<<(nnz + 255) / 256, 256>>>(ni, ei, nnz);
    k_inv<<<(NNODES + 255) / 256, 256>>>();

    // fused tensor-core: y = x @ conv_W ; out = x @ res_W + (res_b + conv_b)
    int gblocks = (M + 63) / 64;
    k_gemm_mma<<<gblocks, 256>>>(x, conv_W, res_W, res_b, conv_b,
                                 (float*)yptr, out, M);

    // scatter: node -> edge, then edge -> node (folding B^-1 and D^-1)
    int sblocks = (nnz + 7) / 8;
    k_scatter_edge<<<sblocks, 256>>>(ni, ei, nnz);
    k_scatter_node<<<sblocks, 256>>>(ni, ei, out, nnz);
}

// round 13
// speedup vs baseline: 1.0687x; 1.0687x over previous
#include <cuda_runtime.h>
#include <cstdint>
#include <cstddef>

#define NNODES 100000
#define NEDGES 20000
#define D 128

// ---- scratch (device globals: allocation-free) ----
__device__ __align__(16) float g_y[(size_t)NNODES * D];      // x @ conv_W
__device__ __align__(16) float g_efeat[(size_t)NEDGES * D];  // hyperedge accum
__device__ int   g_degn[NNODES];
__device__ int   g_dege[NEDGES];
__device__ float g_invn[NNODES];
__device__ float g_inve[NEDGES];

// ---- zero e_feat + degree counters ----
__global__ __launch_bounds__(256) void k_zero() {
    int i = blockIdx.x * blockDim.x + threadIdx.x;
    const int nef4 = (NEDGES * D) / 4;  // 640000 float4
    if (i < nef4) {
        ((float4*)g_efeat)[i] = make_float4(0.f, 0.f, 0.f, 0.f);
    }
    if (i < NNODES) g_degn[i] = 0;
    if (i < NEDGES) g_dege[i] = 0;
}

// ---- degree counts ----
__global__ __launch_bounds__(256) void k_degree(const int* __restrict__ ni,
                                                const int* __restrict__ ei, int nnz) {
    int i = blockIdx.x * blockDim.x + threadIdx.x;
    if (i < nnz) {
        atomicAdd(&g_degn[ni[i]], 1);
        atomicAdd(&g_dege[ei[i]], 1);
    }
}

// ---- 1/deg ----
__global__ __launch_bounds__(256) void k_inv() {
    int i = blockIdx.x * blockDim.x + threadIdx.x;
    if (i < NNODES) {
        int d = g_degn[i];
        g_invn[i] = d > 0 ? 1.0f / (float)d : 0.0f;
    }
    if (i < NEDGES) {
        int d = g_dege[i];
        g_inve[i] = d > 0 ? 1.0f / (float)d : 0.0f;
    }
}

// ---- packed f32x2 FMA (double-rate vs FFMA-3reg) ----
__device__ __forceinline__ void fma2(unsigned long long& d,
                                     unsigned long long a,
                                     unsigned long long b) {
    asm("fma.rn.f32x2 %0, %1, %2, %0;" : "+l"(d) : "l"(a), "l"(b));
}
__device__ __forceinline__ float2 up2(unsigned long long v) {
    float2 r;
    asm("mov.b64 {%0, %1}, %2;" : "=f"(r.x), "=f"(r.y) : "l"(v));
    return r;
}

// ---- fused dual GEMM: C1 = A@B1 ; C2 = A@B2 + (bias1+bias2) ----
// Block tile 64x128, 256 threads, thread tile 8 rows x 4 cols x 2 matrices.
// FFMA2 inner loop with ZERO pack-MOVs:
//   - A stored duplicated in SMEM ([a,a] pairs) -> broadcast LDS.128 gives
//     2 packed row-scalars directly.
//   - B pairs load as ulonglong2 (bit-adjacent floats are already packed).
// Double-buffered SMEM: ONE __syncthreads per k-chunk.
__global__ __launch_bounds__(256, 2) void k_gemm2(const float* __restrict__ A,
                                                  const float* __restrict__ B1,
                                                  const float* __restrict__ B2,
                                                  const float* __restrict__ bias1,
                                                  const float* __restrict__ bias2,
                                                  float* __restrict__ C1,
                                                  float* __restrict__ C2, int M) {
    __shared__ float As[2][8][128];    // [buf][k][2*m (+1 dup)]  4KB/buf
    __shared__ float Bs1[2][8][128];   // [buf][k][n]             4KB/buf
    __shared__ float Bs2[2][8][128];

    const int t    = threadIdx.x;
    const int tx   = t & 31;       // n micro-tile (4 cols)
    const int ty   = t >> 5;       // m micro-tile (8 rows)
    const int row0 = blockIdx.x * 64;

    // A-load mapping: 64 rows x 8 k per chunk; each thread one float2 along k
    const int tm  = t & 63;
    const int tk2 = (t >> 6) * 2;  // 0,2,4,6
    int arow = row0 + tm;
    if (arow >= M) arow = M - 1;   // clamp; epilogue guards writes
    const float* Aptr = A + (size_t)arow * D + tk2;

    // B-load mapping: 8 rows x 128; each thread one float4 from each W
    const int kb = t >> 5;
    const int nb = (t & 31) * 4;

    // packed accumulators: [row][colpair] per matrix (0.0f|0.0f == 0ull)
    unsigned long long acc1[8][2], acc2[8][2];
#pragma unroll
    for (int i = 0; i < 8; i++) {
        acc1[i][0] = 0ull; acc1[i][1] = 0ull;
        acc2[i][0] = 0ull; acc2[i][1] = 0ull;
    }

    // prologue: prefetch chunk 0 into registers
    float2 a_pf  = *(const float2*)(Aptr);
    float4 b1_pf = *(const float4*)&B1[(size_t)kb * D + nb];
    float4 b2_pf = *(const float4*)&B2[(size_t)kb * D + nb];

    for (int kk = 0; kk < 16; kk++) {
        const int buf = kk & 1;
        // ---- stage prefetched chunk into SMEM ----
        *(float2*)&As[buf][tk2][2 * tm]     = make_float2(a_pf.x, a_pf.x);
        *(float2*)&As[buf][tk2 + 1][2 * tm] = make_float2(a_pf.y, a_pf.y);
        *(float4*)&Bs1[buf][kb][nb] = b1_pf;
        *(float4*)&Bs2[buf][kb][nb] = b2_pf;
        __syncthreads();

        // ---- prefetch next chunk (latency hidden under the FFMA2 block) ----
        if (kk + 1 < 16) {
            a_pf  = *(const float2*)(Aptr + (kk + 1) * 8);
            b1_pf = *(const float4*)&B1[(size_t)((kk + 1) * 8 + kb) * D + nb];
            b2_pf = *(const float4*)&B2[(size_t)((kk + 1) * 8 + kb) * D + nb];
        }

        // ---- compute on buf: 8 k-steps x 32 FFMA2 ----
#pragma unroll
        for (int k = 0; k < 8; k++) {
            ulonglong2 b1p = *(const ulonglong2*)&Bs1[buf][k][tx * 4];
            ulonglong2 b2p = *(const ulonglong2*)&Bs2[buf][k][tx * 4];
#pragma unroll
            for (int i2 = 0; i2 < 4; i2++) {
                // broadcast LDS.128: packed [a_r, a_r | a_{r+1}, a_{r+1}]
                ulonglong2 ap =
                    *(const ulonglong2*)&As[buf][k][(ty * 8 + i2 * 2) * 2];
                fma2(acc1[i2 * 2][0], ap.x, b1p.x);
                fma2(acc1[i2 * 2][1], ap.x, b1p.y);
                fma2(acc2[i2 * 2][0], ap.x, b2p.x);
                fma2(acc2[i2 * 2][1], ap.x, b2p.y);
                fma2(acc1[i2 * 2 + 1][0], ap.y, b1p.x);
                fma2(acc1[i2 * 2 + 1][1], ap.y, b1p.y);
                fma2(acc2[i2 * 2 + 1][0], ap.y, b2p.x);
                fma2(acc2[i2 * 2 + 1][1], ap.y, b2p.y);
            }
        }
        // no trailing sync: next iter stores into buf^1, whose last readers
        // (iter kk-1) are ordered by the sync at the top of this iter.
    }

    float4 bias;
    {
        float4 ba = *(const float4*)&bias1[tx * 4];
        float4 bb = *(const float4*)&bias2[tx * 4];
        bias = make_float4(ba.x + bb.x, ba.y + bb.y, ba.z + bb.z, ba.w + bb.w);
    }
#pragma unroll
    for (int i = 0; i < 8; i++) {
        int row = row0 + ty * 8 + i;
        if (row < M) {
            float2 l0 = up2(acc1[i][0]);
            float2 l1 = up2(acc1[i][1]);
            *(float4*)&C1[(size_t)row * D + tx * 4] =
                make_float4(l0.x, l0.y, l1.x, l1.y);
            float2 m0 = up2(acc2[i][0]);
            float2 m1 = up2(acc2[i][1]);
            *(float4*)&C2[(size_t)row * D + tx * 4] =
                make_float4(m0.x + bias.x, m0.y + bias.y,
                            m1.x + bias.z, m1.y + bias.w);
        }
    }
}

__device__ __forceinline__ void red_add_v4(float* p, float4 v) {
    asm volatile("red.global.add.v4.f32 [%0], {%1, %2, %3, %4};"
                 :: "l"(p), "f"(v.x), "f"(v.y), "f"(v.z), "f"(v.w)
                 : "memory");
}

// ---- pass 1: e_feat[edge] += y[node]  (one warp per nz, float4/lane) ----
__global__ __launch_bounds__(256) void k_scatter_edge(const int* __restrict__ ni,
                                                      const int* __restrict__ ei, int nnz) {
    int w = blockIdx.x * 8 + (threadIdx.x >> 5);
    int lane = threadIdx.x & 31;
    if (w >= nnz) return;
    int node = __ldg(&ni[w]);
    int edge = __ldg(&ei[w]);
    float4 v = *(const float4*)&g_y[(size_t)node * D + lane * 4];
    red_add_v4(&g_efeat[(size_t)edge * D + lane * 4], v);
}

// ---- pass 2: out[node] += e_feat[edge] * inv_e[edge] * inv_n[node] ----
__global__ __launch_bounds__(256) void k_scatter_node(const int* __restrict__ ni,
                                                      const int* __restrict__ ei,
                                                      float* __restrict__ out, int nnz) {
    int w = blockIdx.x * 8 + (threadIdx.x >> 5);
    int lane = threadIdx.x & 31;
    if (w >= nnz) return;
    int node = __ldg(&ni[w]);
    int edge = __ldg(&ei[w]);
    float s = g_inve[edge] * g_invn[node];
    float4 v = *(const float4*)&g_efeat[(size_t)edge * D + lane * 4];
    v.x *= s; v.y *= s; v.z *= s; v.w *= s;
    red_add_v4(&out[(size_t)node * D + lane * 4], v);
}

extern "C" void kernel_launch(void* const* d_in, const int* in_sizes, int n_in,
                              void* d_out, int out_size) {
    const float* x      = (const float*)d_in[0];
    const int*   ni     = (const int*)d_in[1];
    const int*   ei     = (const int*)d_in[2];
    const float* conv_W = (const float*)d_in[3];
    const float* conv_b = (const float*)d_in[4];
    const float* res_W  = (const float*)d_in[5];
    const float* res_b  = (const float*)d_in[6];
    float* out = (float*)d_out;

    const int M   = in_sizes[0] / D;   // 100000
    const int nnz = in_sizes[1];       // 600000

    void* yptr = nullptr;
    cudaGetSymbolAddress(&yptr, g_y);

    // zero scratch (e_feat float4s dominate: 640000 elems)
    k_zero<<<(640000 + 255) / 256, 256>>>();

    // degrees
    k_degree<<<(nnz + 255) / 256, 256>>>(ni, ei, nnz);
    k_inv<<<(NNODES + 255) / 256, 256>>>();

    // fused FFMA2: y = x @ conv_W ; out = x @ res_W + (res_b + conv_b)
    int gblocks = (M + 63) / 64;
    k_gemm2<<<gblocks, 256>>>(x, conv_W, res_W, res_b, conv_b,
                              (float*)yptr, out, M);

    // scatter: node -> edge, then edge -> node (folding B^-1 and D^-1)
    int sblocks = (nnz + 7) / 8;
    k_scatter_edge<<<sblocks, 256>>>(ni, ei, nnz);
    k_scatter_node<<<sblocks, 256>>>(ni, ei, out, nnz);
}

// round 14
// speedup vs baseline: 1.2548x; 1.1742x over previous
#include <cuda_runtime.h>
#include <cuda_bf16.h>
#include <cstdint>
#include <cstddef>

#define NNODES 100000
#define NEDGES 20000
#define D 128

// ---- scratch (device globals: allocation-free) ----
__device__ __align__(16) float g_y[(size_t)NNODES * D];      // x @ conv_W
__device__ __align__(16) float g_efeat[(size_t)NEDGES * D];  // hyperedge accum
__device__ int   g_degn[NNODES];
__device__ int   g_dege[NEDGES];
__device__ float g_invn[NNODES];
__device__ float g_inve[NEDGES];
// bf16 split-2 operands
__device__ __align__(16) __nv_bfloat16 g_ahi[(size_t)NNODES * D];
__device__ __align__(16) __nv_bfloat16 g_alo[(size_t)NNODES * D];
__device__ __align__(16) __nv_bfloat16 g_bhi[2 * D * D];  // [mat][k][n]
__device__ __align__(16) __nv_bfloat16 g_blo[2 * D * D];

// ---- zero e_feat + degree counters ----
__global__ __launch_bounds__(256) void k_zero() {
    int i = blockIdx.x * blockDim.x + threadIdx.x;
    const int nef4 = (NEDGES * D) / 4;  // 640000 float4
    if (i < nef4) {
        ((float4*)g_efeat)[i] = make_float4(0.f, 0.f, 0.f, 0.f);
    }
    if (i < NNODES) g_degn[i] = 0;
    if (i < NEDGES) g_dege[i] = 0;
}

// ---- degree counts ----
__global__ __launch_bounds__(256) void k_degree(const int* __restrict__ ni,
                                                const int* __restrict__ ei, int nnz) {
    int i = blockIdx.x * blockDim.x + threadIdx.x;
    if (i < nnz) {
        atomicAdd(&g_degn[ni[i]], 1);
        atomicAdd(&g_dege[ei[i]], 1);
    }
}

// ---- 1/deg ----
__global__ __launch_bounds__(256) void k_inv() {
    int i = blockIdx.x * blockDim.x + threadIdx.x;
    if (i < NNODES) {
        int d = g_degn[i];
        g_invn[i] = d > 0 ? 1.0f / (float)d : 0.0f;
    }
    if (i < NEDGES) {
        int d = g_dege[i];
        g_inve[i] = d > 0 ? 1.0f / (float)d : 0.0f;
    }
}

// ---- split fp32 -> bf16 hi + lo ----
__device__ __forceinline__ void split2(float v, __nv_bfloat16& h, __nv_bfloat16& l) {
    h = __float2bfloat16_rn(v);
    l = __float2bfloat16_rn(v - __bfloat162float(h));
}

// A: x[M,128] -> g_ahi/g_alo (one float4 per thread)
__global__ __launch_bounds__(256) void k_prep_a(const float* __restrict__ x, int n4) {
    int i = blockIdx.x * blockDim.x + threadIdx.x;
    if (i >= n4) return;
    float4 v = ((const float4*)x)[i];
    __nv_bfloat16 h[4], l[4];
    split2(v.x, h[0], l[0]); split2(v.y, h[1], l[1]);
    split2(v.z, h[2], l[2]); split2(v.w, h[3], l[3]);
    ((uint2*)g_ahi)[i] = *(uint2*)h;
    ((uint2*)g_alo)[i] = *(uint2*)l;
}

// B: conv_W, res_W -> g_bhi/g_blo (mat-major)
__global__ __launch_bounds__(256) void k_prep_b(const float* __restrict__ B1,
                                                const float* __restrict__ B2) {
    int i = blockIdx.x * blockDim.x + threadIdx.x;  // 8192 threads, 4 elems each
    if (i >= 2 * D * D / 4) return;
    const float* src = (i < D * D / 4) ? B1 : B2;
    int j = (i < D * D / 4) ? i : i - D * D / 4;
    float4 v = ((const float4*)src)[j];
    __nv_bfloat16 h[4], l[4];
    split2(v.x, h[0], l[0]); split2(v.y, h[1], l[1]);
    split2(v.z, h[2], l[2]); split2(v.w, h[3], l[3]);
    ((uint2*)g_bhi)[i] = *(uint2*)h;
    ((uint2*)g_blo)[i] = *(uint2*)l;
}

// ---- mma / ldmatrix wrappers ----
__device__ __forceinline__ uint32_t s2u(const void* p) {
    return (uint32_t)__cvta_generic_to_shared(p);
}
__device__ __forceinline__ void ldsm4(uint32_t* r, uint32_t addr) {
    asm volatile("ldmatrix.sync.aligned.m8n8.x4.shared.b16 {%0,%1,%2,%3}, [%4];"
                 : "=r"(r[0]), "=r"(r[1]), "=r"(r[2]), "=r"(r[3]) : "r"(addr));
}
__device__ __forceinline__ void ldsm4t(uint32_t* r, uint32_t addr) {
    asm volatile("ldmatrix.sync.aligned.m8n8.x4.trans.shared.b16 {%0,%1,%2,%3}, [%4];"
                 : "=r"(r[0]), "=r"(r[1]), "=r"(r[2]), "=r"(r[3]) : "r"(addr));
}
__device__ __forceinline__ void mma_bf16(float* c, const uint32_t* a,
                                         uint32_t b0, uint32_t b1) {
    asm volatile("mma.sync.aligned.m16n8k16.row.col.f32.bf16.bf16.f32 "
                 "{%0,%1,%2,%3}, {%4,%5,%6,%7}, {%8,%9}, {%0,%1,%2,%3};"
                 : "+f"(c[0]), "+f"(c[1]), "+f"(c[2]), "+f"(c[3])
                 : "r"(a[0]), "r"(a[1]), "r"(a[2]), "r"(a[3]), "r"(b0), "r"(b1));
}

// ---- fused dual GEMM, bf16 split-2 tensor-core ----
// C1 = A@B1 ; C2 = A@B2 + (bias1+bias2), exact-to-~2^-16.
// Block 128 rows x 128 cols x 2 mats; 8 warps: wid = wm*2 + mat.
// Each warp: 32 rows (2 m16 frags) x 128 cols (16 n8 frags) of one matrix.
// 3 terms: Ahi*Bhi + Ahi*Blo + Alo*Bhi.
#define ASTR 24    // A smem row stride (bf16): conflict-free for ldmatrix
#define BSTR 136   // B smem row stride (bf16): conflict-free for ldmatrix.trans
__global__ __launch_bounds__(256, 1) void k_gemm_bf(
    const float* __restrict__ bias1, const float* __restrict__ bias2,
    float* __restrict__ C1, float* __restrict__ C2, int M) {
    __shared__ __nv_bfloat16 As[2][128 * ASTR];      // [part][m*ASTR + k]
    __shared__ __nv_bfloat16 Bs[2][2][16 * BSTR];    // [mat][part][k*BSTR + n]

    const int t    = threadIdx.x;
    const int lane = t & 31;
    const int wid  = t >> 5;
    const int mat  = wid & 1;
    const int wm   = wid >> 1;          // rows wm*32 .. +32
    const int row0 = blockIdx.x * 128;

    // staging maps
    const int arow = t >> 1;            // 0..127
    const int ahalf = (t & 1) * 8;      // k offset 0/8
    int arow_g = row0 + arow;
    if (arow_g >= M) arow_g = M - 1;    // clamp; stores guarded
    const int bk = t >> 4;              // 0..15
    const int bn = (t & 15) * 8;        // 0..120

    // accumulators
    float acc[2][16][4];
#pragma unroll
    for (int f = 0; f < 2; f++)
#pragma unroll
        for (int nt = 0; nt < 16; nt++)
#pragma unroll
            for (int j = 0; j < 4; j++) acc[f][nt][j] = 0.f;

    // loop-invariant ldmatrix addresses
    uint32_t a_addr[2][2], b_addr[2][8];
#pragma unroll
    for (int f = 0; f < 2; f++) {
        int off = (wm * 32 + f * 16 + (lane & 15)) * ASTR + (lane >> 4) * 8;
        a_addr[0][f] = s2u(&As[0][off]);
        a_addr[1][f] = s2u(&As[1][off]);
    }
#pragma unroll
    for (int p = 0; p < 2; p++)
#pragma unroll
        for (int ng = 0; ng < 8; ng++) {
            int off = (lane & 15) * BSTR + ng * 16 + (lane >> 4) * 8;
            b_addr[p][ng] = s2u(&Bs[mat][p][off]);
        }

    // prologue prefetch (chunk 0)
    uint4 pfA0 = *(const uint4*)&g_ahi[(size_t)arow_g * D + ahalf];
    uint4 pfA1 = *(const uint4*)&g_alo[(size_t)arow_g * D + ahalf];
    uint4 pfB[2][2];
#pragma unroll
    for (int m = 0; m < 2; m++) {
        pfB[m][0] = *(const uint4*)&g_bhi[(size_t)m * D * D + bk * D + bn];
        pfB[m][1] = *(const uint4*)&g_blo[(size_t)m * D * D + bk * D + bn];
    }

    for (int kc = 0; kc < 8; kc++) {
        // stage
        *(uint4*)&As[0][arow * ASTR + ahalf] = pfA0;
        *(uint4*)&As[1][arow * ASTR + ahalf] = pfA1;
#pragma unroll
        for (int m = 0; m < 2; m++) {
            *(uint4*)&Bs[m][0][bk * BSTR + bn] = pfB[m][0];
            *(uint4*)&Bs[m][1][bk * BSTR + bn] = pfB[m][1];
        }
        __syncthreads();

        // prefetch next chunk
        if (kc + 1 < 8) {
            int k0 = (kc + 1) * 16;
            pfA0 = *(const uint4*)&g_ahi[(size_t)arow_g * D + k0 + ahalf];
            pfA1 = *(const uint4*)&g_alo[(size_t)arow_g * D + k0 + ahalf];
#pragma unroll
            for (int m = 0; m < 2; m++) {
                pfB[m][0] = *(const uint4*)&g_bhi[(size_t)m * D * D + (k0 + bk) * D + bn];
                pfB[m][1] = *(const uint4*)&g_blo[(size_t)m * D * D + (k0 + bk) * D + bn];
            }
        }

        // a-fragments
        uint32_t ah[2][4], al[2][4];
        ldsm4(ah[0], a_addr[0][0]);
        ldsm4(ah[1], a_addr[0][1]);
        ldsm4(al[0], a_addr[1][0]);
        ldsm4(al[1], a_addr[1][1]);

        // 3 terms: (hi,hi), (hi,lo), (lo,hi)
#pragma unroll
        for (int term = 0; term < 3; term++) {
            const uint32_t(*af)[4] = (term == 2) ? al : ah;
            const int pb = (term == 1) ? 1 : 0;
#pragma unroll
            for (int ng = 0; ng < 8; ng++) {
                uint32_t b[4];
                ldsm4t(b, b_addr[pb][ng]);
                mma_bf16(acc[0][ng * 2],     af[0], b[0], b[1]);
                mma_bf16(acc[0][ng * 2 + 1], af[0], b[2], b[3]);
                mma_bf16(acc[1][ng * 2],     af[1], b[0], b[1]);
                mma_bf16(acc[1][ng * 2 + 1], af[1], b[2], b[3]);
            }
        }
        __syncthreads();
    }

    // epilogue
    const int q = lane & 3, g = lane >> 2;
#pragma unroll
    for (int f = 0; f < 2; f++) {
        int r0 = row0 + wm * 32 + f * 16 + g;
#pragma unroll
        for (int nt = 0; nt < 16; nt++) {
            int c = nt * 8 + q * 2;
            if (mat == 0) {
                if (r0 < M)
                    *(float2*)&C1[(size_t)r0 * D + c] =
                        make_float2(acc[f][nt][0], acc[f][nt][1]);
                if (r0 + 8 < M)
                    *(float2*)&C1[(size_t)(r0 + 8) * D + c] =
                        make_float2(acc[f][nt][2], acc[f][nt][3]);
            } else {
                float bx = bias1[c] + bias2[c];
                float by = bias1[c + 1] + bias2[c + 1];
                if (r0 < M)
                    *(float2*)&C2[(size_t)r0 * D + c] =
                        make_float2(acc[f][nt][0] + bx, acc[f][nt][1] + by);
                if (r0 + 8 < M)
                    *(float2*)&C2[(size_t)(r0 + 8) * D + c] =
                        make_float2(acc[f][nt][2] + bx, acc[f][nt][3] + by);
            }
        }
    }
}

__device__ __forceinline__ void red_add_v4(float* p, float4 v) {
    asm volatile("red.global.add.v4.f32 [%0], {%1, %2, %3, %4};"
                 :: "l"(p), "f"(v.x), "f"(v.y), "f"(v.z), "f"(v.w)
                 : "memory");
}

// ---- pass 1: e_feat[edge] += y[node]  (one warp per nz, float4/lane) ----
__global__ __launch_bounds__(256) void k_scatter_edge(const int* __restrict__ ni,
                                                      const int* __restrict__ ei, int nnz) {
    int w = blockIdx.x * 8 + (threadIdx.x >> 5);
    int lane = threadIdx.x & 31;
    if (w >= nnz) return;
    int node = __ldg(&ni[w]);
    int edge = __ldg(&ei[w]);
    float4 v = *(const float4*)&g_y[(size_t)node * D + lane * 4];
    red_add_v4(&g_efeat[(size_t)edge * D + lane * 4], v);
}

// ---- pass 2: out[node] += e_feat[edge] * inv_e[edge] * inv_n[node] ----
__global__ __launch_bounds__(256) void k_scatter_node(const int* __restrict__ ni,
                                                      const int* __restrict__ ei,
                                                      float* __restrict__ out, int nnz) {
    int w = blockIdx.x * 8 + (threadIdx.x >> 5);
    int lane = threadIdx.x & 31;
    if (w >= nnz) return;
    int node = __ldg(&ni[w]);
    int edge = __ldg(&ei[w]);
    float s = g_inve[edge] * g_invn[node];
    float4 v = *(const float4*)&g_efeat[(size_t)edge * D + lane * 4];
    v.x *= s; v.y *= s; v.z *= s; v.w *= s;
    red_add_v4(&out[(size_t)node * D + lane * 4], v);
}

extern "C" void kernel_launch(void* const* d_in, const int* in_sizes, int n_in,
                              void* d_out, int out_size) {
    const float* x      = (const float*)d_in[0];
    const int*   ni     = (const int*)d_in[1];
    const int*   ei     = (const int*)d_in[2];
    const float* conv_W = (const float*)d_in[3];
    const float* conv_b = (const float*)d_in[4];
    const float* res_W  = (const float*)d_in[5];
    const float* res_b  = (const float*)d_in[6];
    float* out = (float*)d_out;

    const int M   = in_sizes[0] / D;   // 100000
    const int nnz = in_sizes[1];       // 600000

    void* yptr = nullptr;
    cudaGetSymbolAddress(&yptr, g_y);

    // zero scratch + degrees
    k_zero<<<(640000 + 255) / 256, 256>>>();
    k_degree<<<(nnz + 255) / 256, 256>>>(ni, ei, nnz);
    k_inv<<<(NNODES + 255) / 256, 256>>>();

    // bf16 split-2 operand prep
    int n4 = M * D / 4;
    k_prep_a<<<(n4 + 255) / 256, 256>>>(x, n4);
    k_prep_b<<<(2 * D * D / 4 + 255) / 256, 256>>>(conv_W, res_W);

    // fused tensor-core GEMM: y = x@conv_W ; out = x@res_W + (res_b+conv_b)
    int gblocks = (M + 127) / 128;
    k_gemm_bf<<<gblocks, 256>>>(res_b, conv_b, (float*)yptr, out, M);

    // scatter: node -> edge, then edge -> node (folding B^-1 and D^-1)
    int sblocks = (nnz + 7) / 8;
    k_scatter_edge<<<sblocks, 256>>>(ni, ei, nnz);
    k_scatter_node<<<sblocks, 256>>>(ni, ei, out, nnz);
}

// round 15
// speedup vs baseline: 1.3242x; 1.0553x over previous
#include <cuda_runtime.h>
#include <cuda_bf16.h>
#include <cstdint>
#include <cstddef>

#define NNODES 100000
#define NEDGES 20000
#define D 128

// ---- scratch (device globals: allocation-free) ----
__device__ __align__(16) float g_y[(size_t)NNODES * D];      // x @ conv_W
__device__ __align__(16) float g_efeat[(size_t)NEDGES * D];  // hyperedge accum
__device__ int   g_degn[NNODES];
__device__ int   g_dege[NEDGES];
__device__ float g_invn[NNODES];
__device__ float g_inve[NEDGES];
// bf16 split-2 weights (A is split on-the-fly inside the GEMM)
__device__ __align__(16) __nv_bfloat16 g_bhi[2 * D * D];  // [mat][k][n]
__device__ __align__(16) __nv_bfloat16 g_blo[2 * D * D];

// ---- zero e_feat + degree counters ----
__global__ __launch_bounds__(256) void k_zero() {
    int i = blockIdx.x * blockDim.x + threadIdx.x;
    const int nef4 = (NEDGES * D) / 4;  // 640000 float4
    if (i < nef4) {
        ((float4*)g_efeat)[i] = make_float4(0.f, 0.f, 0.f, 0.f);
    }
    if (i < NNODES) g_degn[i] = 0;
    if (i < NEDGES) g_dege[i] = 0;
}

// ---- degree counts ----
__global__ __launch_bounds__(256) void k_degree(const int* __restrict__ ni,
                                                const int* __restrict__ ei, int nnz) {
    int i = blockIdx.x * blockDim.x + threadIdx.x;
    if (i < nnz) {
        atomicAdd(&g_degn[ni[i]], 1);
        atomicAdd(&g_dege[ei[i]], 1);
    }
}

// ---- 1/deg ----
__global__ __launch_bounds__(256) void k_inv() {
    int i = blockIdx.x * blockDim.x + threadIdx.x;
    if (i < NNODES) {
        int d = g_degn[i];
        g_invn[i] = d > 0 ? 1.0f / (float)d : 0.0f;
    }
    if (i < NEDGES) {
        int d = g_dege[i];
        g_inve[i] = d > 0 ? 1.0f / (float)d : 0.0f;
    }
}

// ---- split fp32 -> bf16 hi + lo ----
__device__ __forceinline__ void split2(float v, __nv_bfloat16& h, __nv_bfloat16& l) {
    h = __float2bfloat16_rn(v);
    l = __float2bfloat16_rn(v - __bfloat162float(h));
}

// B: conv_W, res_W -> g_bhi/g_blo (mat-major)
__global__ __launch_bounds__(256) void k_prep_b(const float* __restrict__ B1,
                                                const float* __restrict__ B2) {
    int i = blockIdx.x * blockDim.x + threadIdx.x;  // 8192 threads, 4 elems each
    if (i >= 2 * D * D / 4) return;
    const float* src = (i < D * D / 4) ? B1 : B2;
    int j = (i < D * D / 4) ? i : i - D * D / 4;
    float4 v = ((const float4*)src)[j];
    __nv_bfloat16 h[4], l[4];
    split2(v.x, h[0], l[0]); split2(v.y, h[1], l[1]);
    split2(v.z, h[2], l[2]); split2(v.w, h[3], l[3]);
    ((uint2*)g_bhi)[i] = *(uint2*)h;
    ((uint2*)g_blo)[i] = *(uint2*)l;
}

// ---- mma / ldmatrix wrappers ----
__device__ __forceinline__ uint32_t s2u(const void* p) {
    return (uint32_t)__cvta_generic_to_shared(p);
}
__device__ __forceinline__ void ldsm4(uint32_t* r, uint32_t addr) {
    asm volatile("ldmatrix.sync.aligned.m8n8.x4.shared.b16 {%0,%1,%2,%3}, [%4];"
                 : "=r"(r[0]), "=r"(r[1]), "=r"(r[2]), "=r"(r[3]) : "r"(addr));
}
__device__ __forceinline__ void ldsm4t(uint32_t* r, uint32_t addr) {
    asm volatile("ldmatrix.sync.aligned.m8n8.x4.trans.shared.b16 {%0,%1,%2,%3}, [%4];"
                 : "=r"(r[0]), "=r"(r[1]), "=r"(r[2]), "=r"(r[3]) : "r"(addr));
}
__device__ __forceinline__ void mma_bf16(float* c, const uint32_t* a,
                                         uint32_t b0, uint32_t b1) {
    asm volatile("mma.sync.aligned.m16n8k16.row.col.f32.bf16.bf16.f32 "
                 "{%0,%1,%2,%3}, {%4,%5,%6,%7}, {%8,%9}, {%0,%1,%2,%3};"
                 : "+f"(c[0]), "+f"(c[1]), "+f"(c[2]), "+f"(c[3])
                 : "r"(a[0]), "r"(a[1]), "r"(a[2]), "r"(a[3]), "r"(b0), "r"(b1));
}

// pack 4 floats into hi-bf16x2 pair and lo-bf16x2 pair (8 bf16 total per uint2)
__device__ __forceinline__ void split4pack(float4 v, uint2& hi, uint2& lo) {
    __nv_bfloat16 h[4], l[4];
    split2(v.x, h[0], l[0]); split2(v.y, h[1], l[1]);
    split2(v.z, h[2], l[2]); split2(v.w, h[3], l[3]);
    hi = *(uint2*)h;
    lo = *(uint2*)l;
}

// ---- fused dual GEMM, bf16 split-2 tensor-core, A split on-the-fly ----
// C1 = A@B1 ; C2 = A@B2 + (bias1+bias2), exact-to-~2^-16.
// Block 128 rows x 128 cols x 2 mats; 8 warps: wid = wm*2 + mat.
// Each warp: 32 rows (2 m16 frags) x 128 cols (16 n8 frags) of one matrix.
// 3 terms: Ahi*Bhi + Ahi*Blo + Alo*Bhi.
#define ASTR 24    // A smem row stride (bf16): conflict-free for ldmatrix
#define BSTR 136   // B smem row stride (bf16): conflict-free for ldmatrix.trans
__global__ __launch_bounds__(256, 1) void k_gemm_bf(
    const float* __restrict__ A,
    const float* __restrict__ bias1, const float* __restrict__ bias2,
    float* __restrict__ C1, float* __restrict__ C2, int M) {
    __shared__ __nv_bfloat16 As[2][128 * ASTR];      // [part][m*ASTR + k]
    __shared__ __nv_bfloat16 Bs[2][2][16 * BSTR];    // [mat][part][k*BSTR + n]

    const int t    = threadIdx.x;
    const int lane = t & 31;
    const int wid  = t >> 5;
    const int mat  = wid & 1;
    const int wm   = wid >> 1;          // rows wm*32 .. +32
    const int row0 = blockIdx.x * 128;

    // staging maps
    const int arow = t >> 1;            // 0..127
    const int ahalf = (t & 1) * 8;      // k offset 0/8
    int arow_g = row0 + arow;
    if (arow_g >= M) arow_g = M - 1;    // clamp; stores guarded
    const int bk = t >> 4;              // 0..15
    const int bn = (t & 15) * 8;        // 0..120

    // accumulators
    float acc[2][16][4];
#pragma unroll
    for (int f = 0; f < 2; f++)
#pragma unroll
        for (int nt = 0; nt < 16; nt++)
#pragma unroll
            for (int j = 0; j < 4; j++) acc[f][nt][j] = 0.f;

    // loop-invariant ldmatrix addresses
    uint32_t a_addr[2][2], b_addr[2][8];
#pragma unroll
    for (int f = 0; f < 2; f++) {
        int off = (wm * 32 + f * 16 + (lane & 15)) * ASTR + (lane >> 4) * 8;
        a_addr[0][f] = s2u(&As[0][off]);
        a_addr[1][f] = s2u(&As[1][off]);
    }
#pragma unroll
    for (int p = 0; p < 2; p++)
#pragma unroll
        for (int ng = 0; ng < 8; ng++) {
            int off = (lane & 15) * BSTR + ng * 16 + (lane >> 4) * 8;
            b_addr[p][ng] = s2u(&Bs[mat][p][off]);
        }

    // prologue prefetch (chunk 0): A as raw fp32 (split happens at staging)
    float4 pfx0 = *(const float4*)&A[(size_t)arow_g * D + ahalf];
    float4 pfx1 = *(const float4*)&A[(size_t)arow_g * D + ahalf + 4];
    uint4 pfB[2][2];
#pragma unroll
    for (int m = 0; m < 2; m++) {
        pfB[m][0] = *(const uint4*)&g_bhi[(size_t)m * D * D + bk * D + bn];
        pfB[m][1] = *(const uint4*)&g_blo[(size_t)m * D * D + bk * D + bn];
    }

    for (int kc = 0; kc < 8; kc++) {
        // stage: split A fp32 -> bf16 hi/lo in registers, then STS.128
        {
            uint2 h0, l0, h1, l1;
            split4pack(pfx0, h0, l0);
            split4pack(pfx1, h1, l1);
            uint4 hv = make_uint4(h0.x, h0.y, h1.x, h1.y);
            uint4 lv = make_uint4(l0.x, l0.y, l1.x, l1.y);
            *(uint4*)&As[0][arow * ASTR + ahalf] = hv;
            *(uint4*)&As[1][arow * ASTR + ahalf] = lv;
        }
#pragma unroll
        for (int m = 0; m < 2; m++) {
            *(uint4*)&Bs[m][0][bk * BSTR + bn] = pfB[m][0];
            *(uint4*)&Bs[m][1][bk * BSTR + bn] = pfB[m][1];
        }
        __syncthreads();

        // prefetch next chunk
        if (kc + 1 < 8) {
            int k0 = (kc + 1) * 16;
            pfx0 = *(const float4*)&A[(size_t)arow_g * D + k0 + ahalf];
            pfx1 = *(const float4*)&A[(size_t)arow_g * D + k0 + ahalf + 4];
#pragma unroll
            for (int m = 0; m < 2; m++) {
                pfB[m][0] = *(const uint4*)&g_bhi[(size_t)m * D * D + (k0 + bk) * D + bn];
                pfB[m][1] = *(const uint4*)&g_blo[(size_t)m * D * D + (k0 + bk) * D + bn];
            }
        }

        // a-fragments
        uint32_t ah[2][4], al[2][4];
        ldsm4(ah[0], a_addr[0][0]);
        ldsm4(ah[1], a_addr[0][1]);
        ldsm4(al[0], a_addr[1][0]);
        ldsm4(al[1], a_addr[1][1]);

        // 3 terms: (hi,hi), (hi,lo), (lo,hi)
#pragma unroll
        for (int term = 0; term < 3; term++) {
            const uint32_t(*af)[4] = (term == 2) ? al : ah;
            const int pb = (term == 1) ? 1 : 0;
#pragma unroll
            for (int ng = 0; ng < 8; ng++) {
                uint32_t b[4];
                ldsm4t(b, b_addr[pb][ng]);
                mma_bf16(acc[0][ng * 2],     af[0], b[0], b[1]);
                mma_bf16(acc[0][ng * 2 + 1], af[0], b[2], b[3]);
                mma_bf16(acc[1][ng * 2],     af[1], b[0], b[1]);
                mma_bf16(acc[1][ng * 2 + 1], af[1], b[2], b[3]);
            }
        }
        __syncthreads();
    }

    // epilogue
    const int q = lane & 3, g = lane >> 2;
#pragma unroll
    for (int f = 0; f < 2; f++) {
        int r0 = row0 + wm * 32 + f * 16 + g;
#pragma unroll
        for (int nt = 0; nt < 16; nt++) {
            int c = nt * 8 + q * 2;
            if (mat == 0) {
                if (r0 < M)
                    *(float2*)&C1[(size_t)r0 * D + c] =
                        make_float2(acc[f][nt][0], acc[f][nt][1]);
                if (r0 + 8 < M)
                    *(float2*)&C1[(size_t)(r0 + 8) * D + c] =
                        make_float2(acc[f][nt][2], acc[f][nt][3]);
            } else {
                float bx = bias1[c] + bias2[c];
                float by = bias1[c + 1] + bias2[c + 1];
                if (r0 < M)
                    *(float2*)&C2[(size_t)r0 * D + c] =
                        make_float2(acc[f][nt][0] + bx, acc[f][nt][1] + by);
                if (r0 + 8 < M)
                    *(float2*)&C2[(size_t)(r0 + 8) * D + c] =
                        make_float2(acc[f][nt][2] + bx, acc[f][nt][3] + by);
            }
        }
    }
}

__device__ __forceinline__ void red_add_v4(float* p, float4 v) {
    asm volatile("red.global.add.v4.f32 [%0], {%1, %2, %3, %4};"
                 :: "l"(p), "f"(v.x), "f"(v.y), "f"(v.z), "f"(v.w)
                 : "memory");
}

// ---- pass 1: e_feat[edge] += y[node]  (one warp per nz, float4/lane) ----
__global__ __launch_bounds__(256) void k_scatter_edge(const int* __restrict__ ni,
                                                      const int* __restrict__ ei, int nnz) {
    int w = blockIdx.x * 8 + (threadIdx.x >> 5);
    int lane = threadIdx.x & 31;
    if (w >= nnz) return;
    int node = __ldg(&ni[w]);
    int edge = __ldg(&ei[w]);
    float4 v = *(const float4*)&g_y[(size_t)node * D + lane * 4];
    red_add_v4(&g_efeat[(size_t)edge * D + lane * 4], v);
}

// ---- pass 2: out[node] += e_feat[edge] * inv_e[edge] * inv_n[node] ----
__global__ __launch_bounds__(256) void k_scatter_node(const int* __restrict__ ni,
                                                      const int* __restrict__ ei,
                                                      float* __restrict__ out, int nnz) {
    int w = blockIdx.x * 8 + (threadIdx.x >> 5);
    int lane = threadIdx.x & 31;
    if (w >= nnz) return;
    int node = __ldg(&ni[w]);
    int edge = __ldg(&ei[w]);
    float s = g_inve[edge] * g_invn[node];
    float4 v = *(const float4*)&g_efeat[(size_t)edge * D + lane * 4];
    v.x *= s; v.y *= s; v.z *= s; v.w *= s;
    red_add_v4(&out[(size_t)node * D + lane * 4], v);
}

extern "C" void kernel_launch(void* const* d_in, const int* in_sizes, int n_in,
                              void* d_out, int out_size) {
    const float* x      = (const float*)d_in[0];
    const int*   ni     = (const int*)d_in[1];
    const int*   ei     = (const int*)d_in[2];
    const float* conv_W = (const float*)d_in[3];
    const float* conv_b = (const float*)d_in[4];
    const float* res_W  = (const float*)d_in[5];
    const float* res_b  = (const float*)d_in[6];
    float* out = (float*)d_out;

    const int M   = in_sizes[0] / D;   // 100000
    const int nnz = in_sizes[1];       // 600000

    void* yptr = nullptr;
    cudaGetSymbolAddress(&yptr, g_y);

    // zero scratch + degrees
    k_zero<<<(640000 + 255) / 256, 256>>>();
    k_degree<<<(nnz + 255) / 256, 256>>>(ni, ei, nnz);
    k_inv<<<(NNODES + 255) / 256, 256>>>();

    // bf16 split-2 weight prep (A splits on-the-fly inside the GEMM)
    k_prep_b<<<(2 * D * D / 4 + 255) / 256, 256>>>(conv_W, res_W);

    // fused tensor-core GEMM: y = x@conv_W ; out = x@res_W + (res_b+conv_b)
    int gblocks = (M + 127) / 128;
    k_gemm_bf<<<gblocks, 256>>>(x, res_b, conv_b, (float*)yptr, out, M);

    // scatter: node -> edge, then edge -> node (folding B^-1 and D^-1)
    int sblocks = (nnz + 7) / 8;
    k_scatter_edge<<<sblocks, 256>>>(ni, ei, nnz);
    k_scatter_node<<<sblocks, 256>>>(ni, ei, out, nnz);
}

// round 16
// speedup vs baseline: 1.6993x; 1.2832x over previous
#include <cuda_runtime.h>
#include <cuda_bf16.h>
#include <cstdint>
#include <cstddef>

#define NNODES 100000
#define NEDGES 20000
#define NNZ 600000
#define D 128

// ---- scratch (device globals: allocation-free) ----
__device__ __align__(16) float g_y[(size_t)NNODES * D];      // x @ conv_W
__device__ __align__(16) float g_efeat[(size_t)NEDGES * D];  // hyperedge accum
__device__ int   g_degn[NNODES];
__device__ int   g_dege[NEDGES];
__device__ float g_invn[NNODES];
__device__ float g_inve[NEDGES];
// CSR adjacency (built per call; layout nondeterministic, sums rel_err-stable)
__device__ int g_offe[NEDGES];
__device__ int g_offn[NNODES];
__device__ int g_cure[NEDGES];
__device__ int g_curn[NNODES];
__device__ int g_adj_e[NNZ];   // node ids grouped by edge
__device__ int g_adj_n[NNZ];   // edge ids grouped by node
__device__ int g_tote, g_totn;
// bf16 split-2 weights (A is split on-the-fly inside the GEMM)
__device__ __align__(16) __nv_bfloat16 g_bhi[2 * D * D];  // [mat][k][n]
__device__ __align__(16) __nv_bfloat16 g_blo[2 * D * D];

// ---- zero degree counters + cursors (e_feat no longer needs zeroing) ----
__global__ __launch_bounds__(256) void k_zero() {
    int i = blockIdx.x * blockDim.x + threadIdx.x;
    if (i < NNODES) { g_degn[i] = 0; g_curn[i] = 0; }
    if (i < NEDGES) { g_dege[i] = 0; g_cure[i] = 0; }
    if (i == 0) { g_tote = 0; g_totn = 0; }
}

// ---- degree counts ----
__global__ __launch_bounds__(256) void k_degree(const int* __restrict__ ni,
                                                const int* __restrict__ ei, int nnz) {
    int i = blockIdx.x * blockDim.x + threadIdx.x;
    if (i < nnz) {
        atomicAdd(&g_degn[ni[i]], 1);
        atomicAdd(&g_dege[ei[i]], 1);
    }
}

// ---- 1/deg + CSR offset allocation (warp-aggregated atomic alloc) ----
__global__ __launch_bounds__(256) void k_inv_off() {
    int i = blockIdx.x * blockDim.x + threadIdx.x;
    int lane = threadIdx.x & 31;

    // edges
    {
        int d = (i < NEDGES) ? g_dege[i] : 0;
        int x = d;
#pragma unroll
        for (int o = 1; o < 32; o <<= 1) {
            int y = __shfl_up_sync(0xffffffffu, x, o);
            if (lane >= o) x += y;
        }
        int incl_total = __shfl_sync(0xffffffffu, x, 31);
        int base = 0;
        if (lane == 31 && incl_total > 0) base = atomicAdd(&g_tote, incl_total);
        base = __shfl_sync(0xffffffffu, base, 31);
        if (i < NEDGES) {
            g_offe[i] = base + x - d;
            g_inve[i] = d > 0 ? 1.0f / (float)d : 0.0f;
        }
    }
    // nodes
    {
        int d = (i < NNODES) ? g_degn[i] : 0;
        int x = d;
#pragma unroll
        for (int o = 1; o < 32; o <<= 1) {
            int y = __shfl_up_sync(0xffffffffu, x, o);
            if (lane >= o) x += y;
        }
        int incl_total = __shfl_sync(0xffffffffu, x, 31);
        int base = 0;
        if (lane == 31 && incl_total > 0) base = atomicAdd(&g_totn, incl_total);
        base = __shfl_sync(0xffffffffu, base, 31);
        if (i < NNODES) {
            g_offn[i] = base + x - d;
            g_invn[i] = d > 0 ? 1.0f / (float)d : 0.0f;
        }
    }
}

// ---- fill adjacency lists ----
__global__ __launch_bounds__(256) void k_fill(const int* __restrict__ ni,
                                              const int* __restrict__ ei, int nnz) {
    int i = blockIdx.x * blockDim.x + threadIdx.x;
    if (i >= nnz) return;
    int n = ni[i], e = ei[i];
    int pe = atomicAdd(&g_cure[e], 1);
    g_adj_e[g_offe[e] + pe] = n;
    int pn = atomicAdd(&g_curn[n], 1);
    g_adj_n[g_offn[n] + pn] = e;
}

// ---- split fp32 -> bf16 hi + lo ----
__device__ __forceinline__ void split2(float v, __nv_bfloat16& h, __nv_bfloat16& l) {
    h = __float2bfloat16_rn(v);
    l = __float2bfloat16_rn(v - __bfloat162float(h));
}

// B: conv_W, res_W -> g_bhi/g_blo (mat-major)
__global__ __launch_bounds__(256) void k_prep_b(const float* __restrict__ B1,
                                                const float* __restrict__ B2) {
    int i = blockIdx.x * blockDim.x + threadIdx.x;
    if (i >= 2 * D * D / 4) return;
    const float* src = (i < D * D / 4) ? B1 : B2;
    int j = (i < D * D / 4) ? i : i - D * D / 4;
    float4 v = ((const float4*)src)[j];
    __nv_bfloat16 h[4], l[4];
    split2(v.x, h[0], l[0]); split2(v.y, h[1], l[1]);
    split2(v.z, h[2], l[2]); split2(v.w, h[3], l[3]);
    ((uint2*)g_bhi)[i] = *(uint2*)h;
    ((uint2*)g_blo)[i] = *(uint2*)l;
}

// ---- mma / ldmatrix wrappers ----
__device__ __forceinline__ uint32_t s2u(const void* p) {
    return (uint32_t)__cvta_generic_to_shared(p);
}
__device__ __forceinline__ void ldsm4(uint32_t* r, uint32_t addr) {
    asm volatile("ldmatrix.sync.aligned.m8n8.x4.shared.b16 {%0,%1,%2,%3}, [%4];"
                 : "=r"(r[0]), "=r"(r[1]), "=r"(r[2]), "=r"(r[3]) : "r"(addr));
}
__device__ __forceinline__ void ldsm4t(uint32_t* r, uint32_t addr) {
    asm volatile("ldmatrix.sync.aligned.m8n8.x4.trans.shared.b16 {%0,%1,%2,%3}, [%4];"
                 : "=r"(r[0]), "=r"(r[1]), "=r"(r[2]), "=r"(r[3]) : "r"(addr));
}
__device__ __forceinline__ void mma_bf16(float* c, const uint32_t* a,
                                         uint32_t b0, uint32_t b1) {
    asm volatile("mma.sync.aligned.m16n8k16.row.col.f32.bf16.bf16.f32 "
                 "{%0,%1,%2,%3}, {%4,%5,%6,%7}, {%8,%9}, {%0,%1,%2,%3};"
                 : "+f"(c[0]), "+f"(c[1]), "+f"(c[2]), "+f"(c[3])
                 : "r"(a[0]), "r"(a[1]), "r"(a[2]), "r"(a[3]), "r"(b0), "r"(b1));
}

// pack 4 floats into hi-bf16x2 pair and lo-bf16x2 pair
__device__ __forceinline__ void split4pack(float4 v, uint2& hi, uint2& lo) {
    __nv_bfloat16 h[4], l[4];
    split2(v.x, h[0], l[0]); split2(v.y, h[1], l[1]);
    split2(v.z, h[2], l[2]); split2(v.w, h[3], l[3]);
    hi = *(uint2*)h;
    lo = *(uint2*)l;
}

// ---- fused dual GEMM, bf16 split-2 tensor-core, A split on-the-fly ----
#define ASTR 24
#define BSTR 136
__global__ __launch_bounds__(256, 1) void k_gemm_bf(
    const float* __restrict__ A,
    const float* __restrict__ bias1, const float* __restrict__ bias2,
    float* __restrict__ C1, float* __restrict__ C2, int M) {
    __shared__ __nv_bfloat16 As[2][128 * ASTR];      // [part][m*ASTR + k]
    __shared__ __nv_bfloat16 Bs[2][2][16 * BSTR];    // [mat][part][k*BSTR + n]

    const int t    = threadIdx.x;
    const int lane = t & 31;
    const int wid  = t >> 5;
    const int mat  = wid & 1;
    const int wm   = wid >> 1;
    const int row0 = blockIdx.x * 128;

    const int arow = t >> 1;
    const int ahalf = (t & 1) * 8;
    int arow_g = row0 + arow;
    if (arow_g >= M) arow_g = M - 1;
    const int bk = t >> 4;
    const int bn = (t & 15) * 8;

    float acc[2][16][4];
#pragma unroll
    for (int f = 0; f < 2; f++)
#pragma unroll
        for (int nt = 0; nt < 16; nt++)
#pragma unroll
            for (int j = 0; j < 4; j++) acc[f][nt][j] = 0.f;

    uint32_t a_addr[2][2], b_addr[2][8];
#pragma unroll
    for (int f = 0; f < 2; f++) {
        int off = (wm * 32 + f * 16 + (lane & 15)) * ASTR + (lane >> 4) * 8;
        a_addr[0][f] = s2u(&As[0][off]);
        a_addr[1][f] = s2u(&As[1][off]);
    }
#pragma unroll
    for (int p = 0; p < 2; p++)
#pragma unroll
        for (int ng = 0; ng < 8; ng++) {
            int off = (lane & 15) * BSTR + ng * 16 + (lane >> 4) * 8;
            b_addr[p][ng] = s2u(&Bs[mat][p][off]);
        }

    float4 pfx0 = *(const float4*)&A[(size_t)arow_g * D + ahalf];
    float4 pfx1 = *(const float4*)&A[(size_t)arow_g * D + ahalf + 4];
    uint4 pfB[2][2];
#pragma unroll
    for (int m = 0; m < 2; m++) {
        pfB[m][0] = *(const uint4*)&g_bhi[(size_t)m * D * D + bk * D + bn];
        pfB[m][1] = *(const uint4*)&g_blo[(size_t)m * D * D + bk * D + bn];
    }

    for (int kc = 0; kc < 8; kc++) {
        {
            uint2 h0, l0, h1, l1;
            split4pack(pfx0, h0, l0);
            split4pack(pfx1, h1, l1);
            uint4 hv = make_uint4(h0.x, h0.y, h1.x, h1.y);
            uint4 lv = make_uint4(l0.x, l0.y, l1.x, l1.y);
            *(uint4*)&As[0][arow * ASTR + ahalf] = hv;
            *(uint4*)&As[1][arow * ASTR + ahalf] = lv;
        }
#pragma unroll
        for (int m = 0; m < 2; m++) {
            *(uint4*)&Bs[m][0][bk * BSTR + bn] = pfB[m][0];
            *(uint4*)&Bs[m][1][bk * BSTR + bn] = pfB[m][1];
        }
        __syncthreads();

        if (kc + 1 < 8) {
            int k0 = (kc + 1) * 16;
            pfx0 = *(const float4*)&A[(size_t)arow_g * D + k0 + ahalf];
            pfx1 = *(const float4*)&A[(size_t)arow_g * D + k0 + ahalf + 4];
#pragma unroll
            for (int m = 0; m < 2; m++) {
                pfB[m][0] = *(const uint4*)&g_bhi[(size_t)m * D * D + (k0 + bk) * D + bn];
                pfB[m][1] = *(const uint4*)&g_blo[(size_t)m * D * D + (k0 + bk) * D + bn];
            }
        }

        uint32_t ah[2][4], al[2][4];
        ldsm4(ah[0], a_addr[0][0]);
        ldsm4(ah[1], a_addr[0][1]);
        ldsm4(al[0], a_addr[1][0]);
        ldsm4(al[1], a_addr[1][1]);

#pragma unroll
        for (int term = 0; term < 3; term++) {
            const uint32_t(*af)[4] = (term == 2) ? al : ah;
            const int pb = (term == 1) ? 1 : 0;
#pragma unroll
            for (int ng = 0; ng < 8; ng++) {
                uint32_t b[4];
                ldsm4t(b, b_addr[pb][ng]);
                mma_bf16(acc[0][ng * 2],     af[0], b[0], b[1]);
                mma_bf16(acc[0][ng * 2 + 1], af[0], b[2], b[3]);
                mma_bf16(acc[1][ng * 2],     af[1], b[0], b[1]);
                mma_bf16(acc[1][ng * 2 + 1], af[1], b[2], b[3]);
            }
        }
        __syncthreads();
    }

    const int q = lane & 3, g = lane >> 2;
#pragma unroll
    for (int f = 0; f < 2; f++) {
        int r0 = row0 + wm * 32 + f * 16 + g;
#pragma unroll
        for (int nt = 0; nt < 16; nt++) {
            int c = nt * 8 + q * 2;
            if (mat == 0) {
                if (r0 < M)
                    *(float2*)&C1[(size_t)r0 * D + c] =
                        make_float2(acc[f][nt][0], acc[f][nt][1]);
                if (r0 + 8 < M)
                    *(float2*)&C1[(size_t)(r0 + 8) * D + c] =
                        make_float2(acc[f][nt][2], acc[f][nt][3]);
            } else {
                float bx = bias1[c] + bias2[c];
                float by = bias1[c + 1] + bias2[c + 1];
                if (r0 < M)
                    *(float2*)&C2[(size_t)r0 * D + c] =
                        make_float2(acc[f][nt][0] + bx, acc[f][nt][1] + by);
                if (r0 + 8 < M)
                    *(float2*)&C2[(size_t)(r0 + 8) * D + c] =
                        make_float2(acc[f][nt][2] + bx, acc[f][nt][3] + by);
            }
        }
    }
}

// ---- pass 1 (CSR): e_feat[e] = sum_{n in adj_e[e]} y[n]  (warp per edge) ----
__global__ __launch_bounds__(256) void k_gather_edge() {
    int e = blockIdx.x * 8 + (threadIdx.x >> 5);
    if (e >= NEDGES) return;
    int lane = threadIdx.x & 31;
    int s = g_offe[e], len = g_dege[e];
    float4 acc = make_float4(0.f, 0.f, 0.f, 0.f);
    int j = 0;
    for (; j + 2 <= len; j += 2) {
        int n0 = __ldg(&g_adj_e[s + j]);
        int n1 = __ldg(&g_adj_e[s + j + 1]);
        float4 v0 = *(const float4*)&g_y[(size_t)n0 * D + lane * 4];
        float4 v1 = *(const float4*)&g_y[(size_t)n1 * D + lane * 4];
        acc.x += v0.x + v1.x; acc.y += v0.y + v1.y;
        acc.z += v0.z + v1.z; acc.w += v0.w + v1.w;
    }
    if (j < len) {
        int n0 = __ldg(&g_adj_e[s + j]);
        float4 v0 = *(const float4*)&g_y[(size_t)n0 * D + lane * 4];
        acc.x += v0.x; acc.y += v0.y; acc.z += v0.z; acc.w += v0.w;
    }
    *(float4*)&g_efeat[(size_t)e * D + lane * 4] = acc;
}

// ---- pass 2 (CSR): out[n] += inv_n[n] * sum_e inv_e[e]*e_feat[e] ----
__global__ __launch_bounds__(256) void k_gather_node(float* __restrict__ out) {
    int n = blockIdx.x * 8 + (threadIdx.x >> 5);
    if (n >= NNODES) return;
    int lane = threadIdx.x & 31;
    int s = g_offn[n], len = g_degn[n];
    float4 acc = make_float4(0.f, 0.f, 0.f, 0.f);
    int j = 0;
    for (; j + 2 <= len; j += 2) {
        int e0 = __ldg(&g_adj_n[s + j]);
        int e1 = __ldg(&g_adj_n[s + j + 1]);
        float s0 = __ldg(&g_inve[e0]);
        float s1 = __ldg(&g_inve[e1]);
        float4 v0 = *(const float4*)&g_efeat[(size_t)e0 * D + lane * 4];
        float4 v1 = *(const float4*)&g_efeat[(size_t)e1 * D + lane * 4];
        acc.x += s0 * v0.x + s1 * v1.x; acc.y += s0 * v0.y + s1 * v1.y;
        acc.z += s0 * v0.z + s1 * v1.z; acc.w += s0 * v0.w + s1 * v1.w;
    }
    if (j < len) {
        int e0 = __ldg(&g_adj_n[s + j]);
        float s0 = __ldg(&g_inve[e0]);
        float4 v0 = *(const float4*)&g_efeat[(size_t)e0 * D + lane * 4];
        acc.x += s0 * v0.x; acc.y += s0 * v0.y;
        acc.z += s0 * v0.z; acc.w += s0 * v0.w;
    }
    float sn = g_invn[n];
    float* p = &out[(size_t)n * D + lane * 4];
    float4 o = *(const float4*)p;
    o.x += sn * acc.x; o.y += sn * acc.y;
    o.z += sn * acc.z; o.w += sn * acc.w;
    *(float4*)p = o;
}

extern "C" void kernel_launch(void* const* d_in, const int* in_sizes, int n_in,
                              void* d_out, int out_size) {
    const float* x      = (const float*)d_in[0];
    const int*   ni     = (const int*)d_in[1];
    const int*   ei     = (const int*)d_in[2];
    const float* conv_W = (const float*)d_in[3];
    const float* conv_b = (const float*)d_in[4];
    const float* res_W  = (const float*)d_in[5];
    const float* res_b  = (const float*)d_in[6];
    float* out = (float*)d_out;

    const int M   = in_sizes[0] / D;   // 100000
    const int nnz = in_sizes[1];       // 600000

    void* yptr = nullptr;
    cudaGetSymbolAddress(&yptr, g_y);

    // setup: counters -> degrees -> inv + CSR offsets -> adjacency fill
    k_zero<<<(NNODES + 255) / 256, 256>>>();
    k_degree<<<(nnz + 255) / 256, 256>>>(ni, ei, nnz);
    k_inv_off<<<(NNODES + 255) / 256, 256>>>();
    k_fill<<<(nnz + 255) / 256, 256>>>(ni, ei, nnz);

    // bf16 split-2 weight prep (A splits on-the-fly inside the GEMM)
    k_prep_b<<<(2 * D * D / 4 + 255) / 256, 256>>>(conv_W, res_W);

    // fused tensor-core GEMM: y = x@conv_W ; out = x@res_W + (res_b+conv_b)
    int gblocks = (M + 127) / 128;
    k_gemm_bf<<<gblocks, 256>>>(x, res_b, conv_b, (float*)yptr, out, M);

    // CSR gathers: node -> edge, then edge -> node (no atomics)
    k_gather_edge<<<(NEDGES + 7) / 8, 256>>>();
    k_gather_node<<<(NNODES + 7) / 8, 256>>>(out);
}

// round 17
// speedup vs baseline: 1.8486x; 1.0879x over previous
#include <cuda_runtime.h>
#include <cuda_bf16.h>
#include <cstdint>
#include <cstddef>

#define NNODES 100000
#define NEDGES 20000
#define NNZ 600000
#define D 128

// ---- scratch (device globals: allocation-free) ----
__device__ __align__(16) float g_y[(size_t)NNODES * D];      // x @ conv_W
__device__ __align__(16) float g_efeat[(size_t)NEDGES * D];  // hyperedge accum
__device__ int   g_degn[NNODES];
__device__ int   g_dege[NEDGES];
__device__ float g_invn[NNODES];
__device__ float g_inve[NEDGES];
// CSR adjacency (built per call; layout nondeterministic, sums rel_err-stable)
__device__ int g_offe[NEDGES];
__device__ int g_offn[NNODES];
__device__ int g_cure[NEDGES];   // allocation cursors (pre-init to offsets)
__device__ int g_curn[NNODES];
__device__ int g_adj_e[NNZ];   // node ids grouped by edge
__device__ int g_adj_n[NNZ];   // edge ids grouped by node
__device__ int g_tote, g_totn;
// bf16 split-2 weights (A is split on-the-fly inside the GEMM)
__device__ __align__(16) __nv_bfloat16 g_bhi[2 * D * D];  // [mat][k][n]
__device__ __align__(16) __nv_bfloat16 g_blo[2 * D * D];

// ---- zero degree counters ----
__global__ __launch_bounds__(256) void k_zero() {
    int i = blockIdx.x * blockDim.x + threadIdx.x;
    if (i < NNODES) g_degn[i] = 0;
    if (i < NEDGES) g_dege[i] = 0;
    if (i == 0) { g_tote = 0; g_totn = 0; }
}

// ---- degree counts ----
__global__ __launch_bounds__(256) void k_degree(const int* __restrict__ ni,
                                                const int* __restrict__ ei, int nnz) {
    int i = blockIdx.x * blockDim.x + threadIdx.x;
    if (i < nnz) {
        atomicAdd(&g_degn[ni[i]], 1);
        atomicAdd(&g_dege[ei[i]], 1);
    }
}

// ---- 1/deg + CSR offsets (warp-aggregated alloc); cursors pre-set to offsets ----
__global__ __launch_bounds__(256) void k_inv_off() {
    int i = blockIdx.x * blockDim.x + threadIdx.x;
    int lane = threadIdx.x & 31;

    // edges
    {
        int d = (i < NEDGES) ? g_dege[i] : 0;
        int x = d;
#pragma unroll
        for (int o = 1; o < 32; o <<= 1) {
            int y = __shfl_up_sync(0xffffffffu, x, o);
            if (lane >= o) x += y;
        }
        int incl_total = __shfl_sync(0xffffffffu, x, 31);
        int base = 0;
        if (lane == 31 && incl_total > 0) base = atomicAdd(&g_tote, incl_total);
        base = __shfl_sync(0xffffffffu, base, 31);
        if (i < NEDGES) {
            int off = base + x - d;
            g_offe[i] = off;
            g_cure[i] = off;   // cursor starts at offset: fill needs no offset load
            g_inve[i] = d > 0 ? 1.0f / (float)d : 0.0f;
        }
    }
    // nodes
    {
        int d = (i < NNODES) ? g_degn[i] : 0;
        int x = d;
#pragma unroll
        for (int o = 1; o < 32; o <<= 1) {
            int y = __shfl_up_sync(0xffffffffu, x, o);
            if (lane >= o) x += y;
        }
        int incl_total = __shfl_sync(0xffffffffu, x, 31);
        int base = 0;
        if (lane == 31 && incl_total > 0) base = atomicAdd(&g_totn, incl_total);
        base = __shfl_sync(0xffffffffu, base, 31);
        if (i < NNODES) {
            int off = base + x - d;
            g_offn[i] = off;
            g_curn[i] = off;
            g_invn[i] = d > 0 ? 1.0f / (float)d : 0.0f;
        }
    }
}

// ---- fill adjacency lists (atomic returns the slot directly) ----
__global__ __launch_bounds__(256) void k_fill(const int* __restrict__ ni,
                                              const int* __restrict__ ei, int nnz) {
    int i = blockIdx.x * blockDim.x + threadIdx.x;
    if (i >= nnz) return;
    int n = ni[i], e = ei[i];
    int pe = atomicAdd(&g_cure[e], 1);
    g_adj_e[pe] = n;
    int pn = atomicAdd(&g_curn[n], 1);
    g_adj_n[pn] = e;
}

// ---- split fp32 -> bf16 hi + lo ----
__device__ __forceinline__ void split2(float v, __nv_bfloat16& h, __nv_bfloat16& l) {
    h = __float2bfloat16_rn(v);
    l = __float2bfloat16_rn(v - __bfloat162float(h));
}

// B: conv_W, res_W -> g_bhi/g_blo (mat-major)
__global__ __launch_bounds__(256) void k_prep_b(const float* __restrict__ B1,
                                                const float* __restrict__ B2) {
    int i = blockIdx.x * blockDim.x + threadIdx.x;
    if (i >= 2 * D * D / 4) return;
    const float* src = (i < D * D / 4) ? B1 : B2;
    int j = (i < D * D / 4) ? i : i - D * D / 4;
    float4 v = ((const float4*)src)[j];
    __nv_bfloat16 h[4], l[4];
    split2(v.x, h[0], l[0]); split2(v.y, h[1], l[1]);
    split2(v.z, h[2], l[2]); split2(v.w, h[3], l[3]);
    ((uint2*)g_bhi)[i] = *(uint2*)h;
    ((uint2*)g_blo)[i] = *(uint2*)l;
}

// ---- mma / ldmatrix wrappers ----
__device__ __forceinline__ uint32_t s2u(const void* p) {
    return (uint32_t)__cvta_generic_to_shared(p);
}
__device__ __forceinline__ void ldsm4(uint32_t* r, uint32_t addr) {
    asm volatile("ldmatrix.sync.aligned.m8n8.x4.shared.b16 {%0,%1,%2,%3}, [%4];"
                 : "=r"(r[0]), "=r"(r[1]), "=r"(r[2]), "=r"(r[3]) : "r"(addr));
}
__device__ __forceinline__ void ldsm4t(uint32_t* r, uint32_t addr) {
    asm volatile("ldmatrix.sync.aligned.m8n8.x4.trans.shared.b16 {%0,%1,%2,%3}, [%4];"
                 : "=r"(r[0]), "=r"(r[1]), "=r"(r[2]), "=r"(r[3]) : "r"(addr));
}
__device__ __forceinline__ void mma_bf16(float* c, const uint32_t* a,
                                         uint32_t b0, uint32_t b1) {
    asm volatile("mma.sync.aligned.m16n8k16.row.col.f32.bf16.bf16.f32 "
                 "{%0,%1,%2,%3}, {%4,%5,%6,%7}, {%8,%9}, {%0,%1,%2,%3};"
                 : "+f"(c[0]), "+f"(c[1]), "+f"(c[2]), "+f"(c[3])
                 : "r"(a[0]), "r"(a[1]), "r"(a[2]), "r"(a[3]), "r"(b0), "r"(b1));
}

// pack 4 floats into hi-bf16x2 pair and lo-bf16x2 pair
__device__ __forceinline__ void split4pack(float4 v, uint2& hi, uint2& lo) {
    __nv_bfloat16 h[4], l[4];
    split2(v.x, h[0], l[0]); split2(v.y, h[1], l[1]);
    split2(v.z, h[2], l[2]); split2(v.w, h[3], l[3]);
    hi = *(uint2*)h;
    lo = *(uint2*)l;
}

// ---- dual GEMM, bf16 split-2 tensor-core, one matrix per blockIdx.y ----
// mat 0: C1 = A@B1 ; mat 1: C2 = A@B2 + (bias1+bias2).
// Block 128 rows x 128 cols, 8 warps of 16-row bands; acc = 64 regs/thread
// -> 2 blocks/SM (4 warps/SMSP). Double-buffered SMEM, 1 sync per k-chunk.
#define ASTR 24
#define BSTR 136
__global__ __launch_bounds__(256, 2) void k_gemm_bf2(
    const float* __restrict__ A,
    const float* __restrict__ bias1, const float* __restrict__ bias2,
    float* __restrict__ C1, float* __restrict__ C2, int M) {
    __shared__ __nv_bfloat16 As[2][2][128 * ASTR];   // [buf][part]
    __shared__ __nv_bfloat16 Bs[2][2][16 * BSTR];    // [buf][part]

    const int t    = threadIdx.x;
    const int lane = t & 31;
    const int wid  = t >> 5;          // 16-row band
    const int mat  = blockIdx.y;
    const int row0 = blockIdx.x * 128;

    const __nv_bfloat16* Bhi = g_bhi + (size_t)mat * D * D;
    const __nv_bfloat16* Blo = g_blo + (size_t)mat * D * D;

    // staging maps
    const int arow = t >> 1;            // 0..127
    const int ahalf = (t & 1) * 8;      // k offset 0/8
    int arow_g = row0 + arow;
    if (arow_g >= M) arow_g = M - 1;    // clamp; stores guarded
    const int bk = t >> 4;              // 0..15
    const int bn = (t & 15) * 8;        // 0..120

    float acc[16][4];
#pragma unroll
    for (int nt = 0; nt < 16; nt++)
#pragma unroll
        for (int j = 0; j < 4; j++) acc[nt][j] = 0.f;

    // ldmatrix addresses: [buf][part]
    uint32_t a_addr[2][2], b_addr[2][2];
    {
        int aoff = (wid * 16 + (lane & 15)) * ASTR + (lane >> 4) * 8;
        int boff = (lane & 15) * BSTR + (lane >> 4) * 8;
#pragma unroll
        for (int bf = 0; bf < 2; bf++)
#pragma unroll
            for (int p = 0; p < 2; p++) {
                a_addr[bf][p] = s2u(&As[bf][p][aoff]);
                b_addr[bf][p] = s2u(&Bs[bf][p][boff]);
            }
    }

    // prologue: prefetch + stage chunk 0 into buf 0
    {
        float4 x0 = *(const float4*)&A[(size_t)arow_g * D + ahalf];
        float4 x1 = *(const float4*)&A[(size_t)arow_g * D + ahalf + 4];
        uint4 bh = *(const uint4*)&Bhi[(size_t)bk * D + bn];
        uint4 bl = *(const uint4*)&Blo[(size_t)bk * D + bn];
        uint2 h0, l0, h1, l1;
        split4pack(x0, h0, l0);
        split4pack(x1, h1, l1);
        *(uint4*)&As[0][0][arow * ASTR + ahalf] = make_uint4(h0.x, h0.y, h1.x, h1.y);
        *(uint4*)&As[0][1][arow * ASTR + ahalf] = make_uint4(l0.x, l0.y, l1.x, l1.y);
        *(uint4*)&Bs[0][0][bk * BSTR + bn] = bh;
        *(uint4*)&Bs[0][1][bk * BSTR + bn] = bl;
    }
    __syncthreads();

    for (int kc = 0; kc < 8; kc++) {
        const int buf = kc & 1;

        // prefetch chunk kc+1 (overlaps compute below)
        float4 nx0, nx1; uint4 nbh, nbl;
        if (kc + 1 < 8) {
            int k0 = (kc + 1) * 16;
            nx0 = *(const float4*)&A[(size_t)arow_g * D + k0 + ahalf];
            nx1 = *(const float4*)&A[(size_t)arow_g * D + k0 + ahalf + 4];
            nbh = *(const uint4*)&Bhi[(size_t)(k0 + bk) * D + bn];
            nbl = *(const uint4*)&Blo[(size_t)(k0 + bk) * D + bn];
        }

        // compute on buf
        uint32_t ah[4], al[4];
        ldsm4(ah, a_addr[buf][0]);
        ldsm4(al, a_addr[buf][1]);
#pragma unroll
        for (int term = 0; term < 3; term++) {
            const uint32_t* af = (term == 2) ? al : ah;
            const int pb = (term == 1) ? 1 : 0;
#pragma unroll
            for (int ng = 0; ng < 8; ng++) {
                uint32_t b[4];
                ldsm4t(b, b_addr[buf][pb] + ng * 32);  // 16 bf16 = 32 bytes apart
                mma_bf16(acc[ng * 2],     af, b[0], b[1]);
                mma_bf16(acc[ng * 2 + 1], af, b[2], b[3]);
            }
        }

        // stage chunk kc+1 into buf^1 (safe: buf^1's readers finished pre-sync)
        if (kc + 1 < 8) {
            uint2 h0, l0, h1, l1;
            split4pack(nx0, h0, l0);
            split4pack(nx1, h1, l1);
            *(uint4*)&As[buf ^ 1][0][arow * ASTR + ahalf] =
                make_uint4(h0.x, h0.y, h1.x, h1.y);
            *(uint4*)&As[buf ^ 1][1][arow * ASTR + ahalf] =
                make_uint4(l0.x, l0.y, l1.x, l1.y);
            *(uint4*)&Bs[buf ^ 1][0][bk * BSTR + bn] = nbh;
            *(uint4*)&Bs[buf ^ 1][1][bk * BSTR + bn] = nbl;
            __syncthreads();
        }
    }

    // epilogue
    const int q = lane & 3, g = lane >> 2;
    int r0 = row0 + wid * 16 + g;
#pragma unroll
    for (int nt = 0; nt < 16; nt++) {
        int c = nt * 8 + q * 2;
        if (mat == 0) {
            if (r0 < M)
                *(float2*)&C1[(size_t)r0 * D + c] =
                    make_float2(acc[nt][0], acc[nt][1]);
            if (r0 + 8 < M)
                *(float2*)&C1[(size_t)(r0 + 8) * D + c] =
                    make_float2(acc[nt][2], acc[nt][3]);
        } else {
            float bx = bias1[c] + bias2[c];
            float by = bias1[c + 1] + bias2[c + 1];
            if (r0 < M)
                *(float2*)&C2[(size_t)r0 * D + c] =
                    make_float2(acc[nt][0] + bx, acc[nt][1] + by);
            if (r0 + 8 < M)
                *(float2*)&C2[(size_t)(r0 + 8) * D + c] =
                    make_float2(acc[nt][2] + bx, acc[nt][3] + by);
        }
    }
}

// ---- pass 1 (CSR): e_feat[e] = sum_{n in adj_e[e]} y[n]  (warp per edge) ----
__global__ __launch_bounds__(256) void k_gather_edge() {
    int e = blockIdx.x * 8 + (threadIdx.x >> 5);
    if (e >= NEDGES) return;
    int lane = threadIdx.x & 31;
    int s = g_offe[e], len = g_dege[e];
    float4 acc = make_float4(0.f, 0.f, 0.f, 0.f);
    int j = 0;
    for (; j + 2 <= len; j += 2) {
        int n0 = __ldg(&g_adj_e[s + j]);
        int n1 = __ldg(&g_adj_e[s + j + 1]);
        float4 v0 = *(const float4*)&g_y[(size_t)n0 * D + lane * 4];
        float4 v1 = *(const float4*)&g_y[(size_t)n1 * D + lane * 4];
        acc.x += v0.x + v1.x; acc.y += v0.y + v1.y;
        acc.z += v0.z + v1.z; acc.w += v0.w + v1.w;
    }
    if (j < len) {
        int n0 = __ldg(&g_adj_e[s + j]);
        float4 v0 = *(const float4*)&g_y[(size_t)n0 * D + lane * 4];
        acc.x += v0.x; acc.y += v0.y; acc.z += v0.z; acc.w += v0.w;
    }
    *(float4*)&g_efeat[(size_t)e * D + lane * 4] = acc;
}

// ---- pass 2 (CSR): out[n] += inv_n[n] * sum_e inv_e[e]*e_feat[e] ----
__global__ __launch_bounds__(256) void k_gather_node(float* __restrict__ out) {
    int n = blockIdx.x * 8 + (threadIdx.x >> 5);
    if (n >= NNODES) return;
    int lane = threadIdx.x & 31;
    int s = g_offn[n], len = g_degn[n];
    float4 acc = make_float4(0.f, 0.f, 0.f, 0.f);
    int j = 0;
    for (; j + 2 <= len; j += 2) {
        int e0 = __ldg(&g_adj_n[s + j]);
        int e1 = __ldg(&g_adj_n[s + j + 1]);
        float s0 = __ldg(&g_inve[e0]);
        float s1 = __ldg(&g_inve[e1]);
        float4 v0 = *(const float4*)&g_efeat[(size_t)e0 * D + lane * 4];
        float4 v1 = *(const float4*)&g_efeat[(size_t)e1 * D + lane * 4];
        acc.x += s0 * v0.x + s1 * v1.x; acc.y += s0 * v0.y + s1 * v1.y;
        acc.z += s0 * v0.z + s1 * v1.z; acc.w += s0 * v0.w + s1 * v1.w;
    }
    if (j < len) {
        int e0 = __ldg(&g_adj_n[s + j]);
        float s0 = __ldg(&g_inve[e0]);
        float4 v0 = *(const float4*)&g_efeat[(size_t)e0 * D + lane * 4];
        acc.x += s0 * v0.x; acc.y += s0 * v0.y;
        acc.z += s0 * v0.z; acc.w += s0 * v0.w;
    }
    float sn = g_invn[n];
    float* p = &out[(size_t)n * D + lane * 4];
    float4 o = *(const float4*)p;
    o.x += sn * acc.x; o.y += sn * acc.y;
    o.z += sn * acc.z; o.w += sn * acc.w;
    *(float4*)p = o;
}

extern "C" void kernel_launch(void* const* d_in, const int* in_sizes, int n_in,
                              void* d_out, int out_size) {
    const float* x      = (const float*)d_in[0];
    const int*   ni     = (const int*)d_in[1];
    const int*   ei     = (const int*)d_in[2];
    const float* conv_W = (const float*)d_in[3];
    const float* conv_b = (const float*)d_in[4];
    const float* res_W  = (const float*)d_in[5];
    const float* res_b  = (const float*)d_in[6];
    float* out = (float*)d_out;

    const int M   = in_sizes[0] / D;   // 100000
    const int nnz = in_sizes[1];       // 600000

    void* yptr = nullptr;
    cudaGetSymbolAddress(&yptr, g_y);

    // setup: counters -> degrees -> inv + CSR offsets (cursors=offsets) -> fill
    k_zero<<<(NNODES + 255) / 256, 256>>>();
    k_degree<<<(nnz + 255) / 256, 256>>>(ni, ei, nnz);
    k_inv_off<<<(NNODES + 255) / 256, 256>>>();
    k_fill<<<(nnz + 255) / 256, 256>>>(ni, ei, nnz);

    // bf16 split-2 weight prep (A splits on-the-fly inside the GEMM)
    k_prep_b<<<(2 * D * D / 4 + 255) / 256, 256>>>(conv_W, res_W);

    // tensor-core GEMM: y = x@conv_W (mat 0) ; out = x@res_W + biases (mat 1)
    dim3 ggrid((M + 127) / 128, 2);
    k_gemm_bf2<<<ggrid, 256>>>(x, res_b, conv_b, (float*)yptr, out, M);

    // CSR gathers: node -> edge, then edge -> node (no atomics)
    k_gather_edge<<<(NEDGES + 7) / 8, 256>>>();
    k_gather_node<<<(NNODES + 7) / 8, 256>>>(out);
}